// round 5
// baseline (speedup 1.0000x reference)
#include <cuda_runtime.h>
#include <math.h>

#define N_    4096
#define V_    2
#define W_    32
#define H_    16
#define M_    512
#define MH_   256          // M_/2 : packed pair count
#define EPSF  1e-6f
#define PIF   3.14159265358979323846f

typedef unsigned long long u64;

// ---------- packed f32x2 helpers (sm_103a FFMA2 path) ----------
__device__ __forceinline__ u64 pk2(float a, float b) {
    u64 r; asm("mov.b64 %0, {%1, %2};" : "=l"(r) : "f"(a), "f"(b)); return r;
}
__device__ __forceinline__ float2 upk2(u64 v) {
    float2 r; asm("mov.b64 {%0, %1}, %2;" : "=f"(r.x), "=f"(r.y) : "l"(v)); return r;
}
__device__ __forceinline__ u64 fma2(u64 a, u64 b, u64 c) {
    u64 d; asm("fma.rn.f32x2 %0, %1, %2, %3;" : "=l"(d) : "l"(a), "l"(b), "l"(c)); return d;
}
__device__ __forceinline__ u64 mul2(u64 a, u64 b) {
    u64 d; asm("mul.rn.f32x2 %0, %1, %2;" : "=l"(d) : "l"(a), "l"(b)); return d;
}
__device__ __forceinline__ u64 add2(u64 a, u64 b) {
    u64 d; asm("add.rn.f32x2 %0, %1, %2;" : "=l"(d) : "l"(a), "l"(b)); return d;
}
__device__ __forceinline__ float rsq_fast(float x) {
    float r; asm("rsqrt.approx.f32 %0, %1;" : "=f"(r) : "f"(x)); return r;
}
__device__ __forceinline__ float rcp_fast(float x) {
    float r; asm("rcp.approx.f32 %0, %1;" : "=f"(r) : "f"(x)); return r;
}

#define ABSM 0x7FFFFFFF7FFFFFFFULL

// Pre-paired per-m tables: component c packed as (sample p, sample p+256).
__device__ float4 g_xy[MH_];  // (lxA, lxB, lyA, lyB)
__device__ float4 g_zw[MH_];  // (lzA, lzB, LiR_A*sa, LiR_B*sa)
__device__ float4 g_gb[MH_];  // (LiG_A*sa, LiG_B*sa, LiB_A*sa, LiB_B*sa)

__global__ void hdr_prep_kernel(const float* __restrict__ env_map)
{
    const int p = blockIdx.x * blockDim.x + threadIdx.x;
    if (p >= MH_) return;
    float lx[2], ly[2], lz[2], er[2], eg[2], eb[2];
    #pragma unroll
    for (int h = 0; h < 2; ++h) {
        const int m = p + h * MH_;
        const int j = m >> 5;          // theta index (H)
        const int i = m & (W_ - 1);    // phi index (W)
        const float theta = ((float)j + 0.5f) * (1.0f / (float)H_) * PIF;
        const float phi   = ((float)i + 0.5f) * (1.0f / (float)W_) * (2.0f * PIF) + 0.5f * PIF;
        float st, ct, sp, cp;
        sincosf(theta, &st, &ct);
        sincosf(phi,   &sp, &cp);
        const float sa = st * ((PIF / (float)H_) * (2.0f * PIF / (float)W_));
        // bilinear grid_sample degenerates to exact texel fetch: Li = env_map[0, i, j, :]
        const float* e = env_map + (i * H_ + j) * 3;
        lx[h] = st * cp;  ly[h] = ct;  lz[h] = -st * sp;
        er[h] = e[0] * sa; eg[h] = e[1] * sa; eb[h] = e[2] * sa;
    }
    g_xy[p] = make_float4(lx[0], lx[1], ly[0], ly[1]);
    g_zw[p] = make_float4(lz[0], lz[1], er[0], er[1]);
    g_gb[p] = make_float4(eg[0], eg[1], eb[0], eb[1]);
}

__global__ __launch_bounds__(256) void hdr_render_kernel(
    const float* __restrict__ normals,
    const float* __restrict__ albedo,
    const float* __restrict__ metallic,
    const float* __restrict__ smoothness,
    const float* __restrict__ viewdirs,
    const float* __restrict__ env_vis,
    float* __restrict__ out)
{
    const int tid   = threadIdx.x;
    const int gwarp = (blockIdx.x * 256 + tid) >> 5;   // pair = n*V + vi
    const int lane  = tid & 31;
    const int n     = gwarp >> 1;

    // ---- warp-invariant scalar setup ----
    float nx = normals[n * 3 + 0];
    float ny = normals[n * 3 + 1];
    float nz = normals[n * 3 + 2];
    {
        const float inv = rsqrtf(fmaxf(fmaf(nx, nx, fmaf(ny, ny, nz * nz)), 1e-24f));
        nx *= inv; ny *= inv; nz *= inv;
    }
    const float* vd = viewdirs + gwarp * 3;
    float vx = vd[0], vy = vd[1], vz = vd[2];
    {
        const float inv = rsqrtf(fmaxf(fmaf(vx, vx, fmaf(vy, vy, vz * vz)), 1e-24f));
        vx *= inv; vy *= inv; vz *= inv;
    }

    const float met    = metallic[n];
    const float rough  = 1.0f - smoothness[n];
    const float alpha  = rough * rough;
    const float alpha2 = alpha * alpha;
    const float a2m1   = alpha2 - 1.0f;
    const float k      = 0.5f * alpha;
    const float omk    = 1.0f - k;
    const float k_eps  = k + EPSF;

    const float ar = albedo[n * 3 + 0];
    const float ag = albedo[n * 3 + 1];
    const float ab = albedo[n * 3 + 2];
    const float f0r = fmaf(ar - 0.04f, met, 0.04f);
    const float f0g = fmaf(ag - 0.04f, met, 0.04f);
    const float f0b = fmaf(ab - 0.04f, met, 0.04f);

    const float NdotV = fmaxf(fmaf(nx, vx, fmaf(ny, vy, nz * vz)), EPSF);
    const float Gv    = NdotV / fmaf(NdotV, omk, k_eps);
    const float a2Gv  = alpha2 * Gv;

    const float dcom = (1.0f - met) * (1.0f / PIF);
    const float dR = dcom * ar, dG = dcom * ag, dB = dcom * ab;

    // ---- packed (splat) constants ----
    const u64 VX2 = pk2(vx, vx), VY2 = pk2(vy, vy), VZ2 = pk2(vz, vz);
    const u64 NX2 = pk2(nx, nx), NY2 = pk2(ny, ny), NZ2 = pk2(nz, nz);
    const u64 ONE2   = pk2(1.0f, 1.0f);
    const u64 NEG1_2 = pk2(-1.0f, -1.0f);
    const u64 HALF2  = pk2(0.5f, 0.5f);
    const u64 EPS2   = pk2(EPSF, EPSF);
    const u64 NEPS2  = pk2(-EPSF, -EPSF);
    const u64 PI2    = pk2(PIF, PIF);
    const u64 A2M1Q2 = pk2(0.25f * a2m1, 0.25f * a2m1);   // folds (2*max)^2 = 4*NdotH^2
    const u64 OMK2   = pk2(omk, omk);
    const u64 KEPS2  = pk2(k_eps, k_eps);
    const u64 FNDV2  = pk2(4.0f * NdotV, 4.0f * NdotV);
    const u64 A2GV2  = pk2(a2Gv, a2Gv);
    const u64 F0R2 = pk2(f0r, f0r), F0G2 = pk2(f0g, f0g), F0B2 = pk2(f0b, f0b);
    const u64 OFR2 = pk2(1.0f - f0r, 1.0f - f0r);
    const u64 OFG2 = pk2(1.0f - f0g, 1.0f - f0g);
    const u64 OFB2 = pk2(1.0f - f0b, 1.0f - f0b);
    const u64 DR2 = pk2(dR, dR), DG2 = pk2(dG, dG), DB2 = pk2(dB, dB);
    const u64 NDR2 = pk2(-dR, -dR), NDG2 = pk2(-dG, -dG), NDB2 = pk2(-dB, -dB);

    const float*  __restrict__ vis = env_vis + n * M_;
    const float4* __restrict__ txy = g_xy;
    const float4* __restrict__ tzw = g_zw;
    const float4* __restrict__ tgb = g_gb;

    u64 ACR = 0ull, ACG = 0ull, ACB = 0ull;   // packed (0.f, 0.f)

    #pragma unroll 2
    for (int p = lane; p < MH_; p += 32) {
        const float4 xy = txy[p];   // lxA,lxB,lyA,lyB
        const float4 zw = tzw[p];   // lzA,lzB,liR pair
        const float4 gb = tgb[p];   // liG pair, liB pair
        const u64 LX = pk2(xy.x, xy.y), LY = pk2(xy.z, xy.w);
        const u64 LZ = pk2(zw.x, zw.y), LR = pk2(zw.z, zw.w);
        const u64 LG = pk2(gb.x, gb.y), LB = pk2(gb.z, gb.w);
        const u64 VIS = pk2(vis[p], vis[p + MH_]);

        // half vector (explicit — reference rounding path)
        const u64 HX = add2(LX, VX2);
        const u64 HY = add2(LY, VY2);
        const u64 HZ = add2(LZ, VZ2);
        const u64 HH = fma2(HX, HX, fma2(HY, HY, mul2(HZ, HZ)));
        const float2 hh = upk2(HH);
        const u64 HINV = pk2(rsq_fast(fmaxf(hh.x, 1e-24f)),
                             rsq_fast(fmaxf(hh.y, 1e-24f)));

        // NdotL = max(n.l, EPS)
        const u64 NL = fma2(LX, NX2, fma2(LY, NY2, mul2(LZ, NZ2)));
        const u64 T0 = add2(NL, NEPS2);
        const u64 NDL = fma2(add2(T0, T0 & ABSM), HALF2, EPS2);

        // NdotH^2 with max(.,0) folded: SS = 2*max(x,0), SS^2 = 4 NdotH^2
        const u64 NHR = fma2(NX2, HX, fma2(NY2, HY, mul2(NZ2, HZ)));
        const u64 NH  = mul2(NHR, HINV);
        const u64 SSx = add2(NH, NH & ABSM);
        const u64 DD  = fma2(mul2(SSx, SSx), A2M1Q2, ONE2);

        const u64 DEN1 = fma2(mul2(DD, PI2), DD, EPS2);
        const u64 DEN2 = fma2(NDL, OMK2, KEPS2);
        const u64 DEN3 = fma2(FNDV2, NDL, EPS2);
        const u64 DEN  = mul2(DEN1, mul2(DEN2, DEN3));
        const float2 dv = upk2(DEN);
        const u64 RCPD = pk2(rcp_fast(dv.x), rcp_fast(dv.y));
        const u64 S    = mul2(mul2(A2GV2, NDL), RCPD);

        // Fresnel: t = 1 - VdotH  (VdotH = l.h/|h| >= 0 analytically; clamps dropped)
        const u64 VHR = fma2(LX, HX, fma2(LY, HY, mul2(LZ, HZ)));
        const u64 VH  = mul2(VHR, HINV);
        const u64 Tt  = fma2(VH, NEG1_2, ONE2);
        const u64 T2  = mul2(Tt, Tt);
        const u64 P5  = mul2(mul2(T2, T2), Tt);

        const u64 Wt = mul2(VIS, NDL);   // sa pre-folded into Li tables

        const u64 FR = fma2(OFR2, P5, F0R2);
        const u64 FG = fma2(OFG2, P5, F0G2);
        const u64 FB = fma2(OFB2, P5, F0B2);

        ACR = fma2(mul2(LR, Wt), fma2(FR, add2(S, NDR2), DR2), ACR);
        ACG = fma2(mul2(LG, Wt), fma2(FG, add2(S, NDG2), DG2), ACG);
        ACB = fma2(mul2(LB, Wt), fma2(FB, add2(S, NDB2), DB2), ACB);
    }

    // collapse packed halves, then warp tree-reduce
    const float2 cr = upk2(ACR);
    const float2 cg = upk2(ACG);
    const float2 cb = upk2(ACB);
    float accR = cr.x + cr.y;
    float accG = cg.x + cg.y;
    float accB = cb.x + cb.y;

    #pragma unroll
    for (int off = 16; off > 0; off >>= 1) {
        accR += __shfl_down_sync(0xffffffffu, accR, off);
        accG += __shfl_down_sync(0xffffffffu, accG, off);
        accB += __shfl_down_sync(0xffffffffu, accB, off);
    }

    if (lane == 0) {
        float* o = out + gwarp * 3;
        o[0] = accR;
        o[1] = accG;
        o[2] = accB;
    }
}

extern "C" void kernel_launch(void* const* d_in, const int* in_sizes, int n_in,
                              void* d_out, int out_size)
{
    const float* normals    = (const float*)d_in[0];
    const float* albedo     = (const float*)d_in[1];
    const float* metallic   = (const float*)d_in[2];
    const float* smoothness = (const float*)d_in[3];
    const float* viewdirs   = (const float*)d_in[4];
    const float* env_vis    = (const float*)d_in[5];
    const float* env_map    = (const float*)d_in[6];
    float* out = (float*)d_out;

    hdr_prep_kernel<<<1, MH_>>>(env_map);

    const int pairs   = N_ * V_;                // 8192 warps
    const int threads = 256;
    const int blocks  = pairs * 32 / threads;   // 1024

    hdr_render_kernel<<<blocks, threads>>>(normals, albedo, metallic, smoothness,
                                           viewdirs, env_vis, out);
}